// round 7
// baseline (speedup 1.0000x reference)
#include <cuda_runtime.h>
#include <math.h>

#define GAMMA 0.99f
#define TAUF  0.95f

constexpr int THREADS = 256;
constexpr int ITEMS   = 8;
constexpr int CHUNK   = THREADS * ITEMS;   // 2048
constexpr int NWARPS  = THREADS / 32;      // 8
constexpr int NB_MAX  = 65536;

// Decoupled-lookback state (device globals; no allocation allowed)
__device__ volatile int g_status[NB_MAX];   // 0=invalid 1=aggregate 2=inclusive
__device__ float4 g_agg[NB_MAX];            // block affine summary (av,bv,aa,ba)
__device__ float2 g_incl[NB_MAX];           // inclusive carry VALUE after this block
__device__ float2 g_part[NB_MAX];           // per-block (sumA, sumA2)
__device__ float2 g_normc;                  // (mean, inv_std)

__device__ __forceinline__ float4 ident4() { return make_float4(1.f, 0.f, 1.f, 0.f); }

// lo∘hi: hi applied first. result = f_lo(f_hi(c))
__device__ __forceinline__ float4 comp4(float4 lo, float4 hi) {
    float4 o;
    o.x = lo.x * hi.x;
    o.y = lo.y + lo.x * hi.y;
    o.z = lo.z * hi.z;
    o.w = lo.w + lo.z * hi.w;
    return o;
}

__device__ __forceinline__ float4 shfl_down4(float4 v, int d) {
    float4 o;
    o.x = __shfl_down_sync(0xffffffffu, v.x, d);
    o.y = __shfl_down_sync(0xffffffffu, v.y, d);
    o.z = __shfl_down_sync(0xffffffffu, v.z, d);
    o.w = __shfl_down_sync(0xffffffffu, v.w, d);
    return o;
}

// Inclusive SUFFIX scan within a warp; ALL 32 lanes execute.
__device__ __forceinline__ float4 warp_suffix_scan(float4 v, int lane) {
#pragma unroll
    for (int d = 1; d < 32; d <<= 1) {
        float4 o = shfl_down4(v, d);
        if (lane + d < 32) v = comp4(v, o);
    }
    return v;
}

__device__ __forceinline__ float4 crosswarp_suffix_scan(float4 v, int lane, int n) {
#pragma unroll
    for (int d = 1; d < 32; d <<= 1) {
        if (d >= n) break;
        float4 o = shfl_down4(v, d);
        if (lane + d < n) v = comp4(v, o);
    }
    return v;
}

struct Tile {
    float rr[ITEMS];   // r
    float dd[ITEMS];   // delta
    float a1[ITEMS];   // gamma * mask
    int   nvalid;
};

__device__ __forceinline__ void load_tile(const float* __restrict__ r,
                                          const float* __restrict__ v,
                                          const int*   __restrict__ m,
                                          long s, long B, Tile& td) {
    float vv[ITEMS + 1];
    long rem = B - s;
    td.nvalid = (rem >= ITEMS) ? ITEMS : (rem > 0 ? (int)rem : 0);
    if (td.nvalid == ITEMS) {
#pragma unroll
        for (int j = 0; j < ITEMS / 4; j++) {
            float4 x = *reinterpret_cast<const float4*>(r + s + 4 * j);
            float4 y = *reinterpret_cast<const float4*>(v + s + 4 * j);
            int4  mi = *reinterpret_cast<const int4*>(m + s + 4 * j);
            td.rr[4*j+0] = x.x; td.rr[4*j+1] = x.y; td.rr[4*j+2] = x.z; td.rr[4*j+3] = x.w;
            vv[4*j+0] = y.x; vv[4*j+1] = y.y; vv[4*j+2] = y.z; vv[4*j+3] = y.w;
            td.a1[4*j+0] = GAMMA * (float)mi.x; td.a1[4*j+1] = GAMMA * (float)mi.y;
            td.a1[4*j+2] = GAMMA * (float)mi.z; td.a1[4*j+3] = GAMMA * (float)mi.w;
        }
        vv[ITEMS] = (s + ITEMS < B) ? v[s + ITEMS] : 0.f;
    } else {
#pragma unroll
        for (int i = 0; i < ITEMS; i++) {
            if (i < td.nvalid) {
                td.rr[i] = r[s + i];
                vv[i]    = v[s + i];
                td.a1[i] = GAMMA * (float)m[s + i];
            } else { td.rr[i] = 0.f; vv[i] = 0.f; td.a1[i] = 0.f; }
        }
        vv[ITEMS] = 0.f;
    }
#pragma unroll
    for (int i = 0; i < ITEMS; i++)
        td.dd[i] = td.rr[i] + td.a1[i] * vv[i + 1] - vv[i];
}

__device__ __forceinline__ float4 tile_summary(const Tile& td) {
    float av = 1.f, bv = 0.f, aa = 1.f, ba = 0.f;
#pragma unroll
    for (int i = 0; i < ITEMS; i++) {
        if (i < td.nvalid) {
            float a1 = td.a1[i];
            float a2 = a1 * TAUF;
            bv = bv + av * td.rr[i]; av = av * a1;
            ba = ba + aa * td.dd[i]; aa = aa * a2;
        }
    }
    return make_float4(av, bv, aa, ba);
}

// ---------------- init: reset lookback flags ----------------
__global__ void k_init(int NB) {
    int i = blockIdx.x * blockDim.x + threadIdx.x;
    if (i < NB) g_status[i] = 0;
}

// ---------------- single-pass scan with decoupled lookback ----------------
__global__ void __launch_bounds__(THREADS) k_scan(const float* __restrict__ r,
                                                  const float* __restrict__ v,
                                                  const int* __restrict__ m,
                                                  float* __restrict__ outA,
                                                  float* __restrict__ outVT,
                                                  long B, int NB) {
    __shared__ float4 WAGG[NWARPS];
    __shared__ float2 WC[NWARPS];
    __shared__ float2 WSUM[NWARPS];
    int t = threadIdx.x, lane = t & 31, w = t >> 5;
    int p = blockIdx.x;                 // processing order
    int ti = NB - 1 - p;                // tile index (from the end)
    long s = (long)ti * CHUNK + (long)t * ITEMS;

    Tile td;
    load_tile(r, v, m, s, B, td);
    float4 f = tile_summary(td);
    float4 sfx = warp_suffix_scan(f, lane);
    if (lane == 0) WAGG[w] = sfx;
    __syncthreads();

    if (w == 0) {
        float4 sw = (lane < NWARPS) ? WAGG[lane] : ident4();
        sw = crosswarp_suffix_scan(sw, lane, NWARPS);
        // lane 0 holds the block aggregate F
        float2 cb;
        if (lane == 0) {
            float4 F = sw;
            if (p > 0) {
                g_agg[p] = F;
                __threadfence();
                g_status[p] = 1;                   // AGGREGATE available
                // lookback: carry_p = F_{p-1}(F_{p-2}(...(incl_q)...))
                float4 H = ident4();
                int q = p - 1;
                for (;;) {
                    int stv;
                    while ((stv = g_status[q]) == 0) __nanosleep(32);
                    __threadfence();               // acquire payload
                    if (stv == 2) {
                        volatile float* ip = (volatile float*)&g_incl[q];
                        float ix = ip[0];
                        float iy = ip[1];
                        cb.x = H.y + H.x * ix;
                        cb.y = H.w + H.z * iy;
                        break;
                    } else {
                        volatile float* ap = (volatile float*)&g_agg[q];
                        float4 a;
                        a.x = ap[0]; a.y = ap[1]; a.z = ap[2]; a.w = ap[3];
                        H = comp4(H, a);
                        q--;
                    }
                }
            } else {
                cb = make_float2(0.f, 0.f);
            }
            // inclusive value after applying this block
            float incx = F.y + F.x * cb.x;
            float incy = F.w + F.z * cb.y;
            volatile float* op = (volatile float*)&g_incl[p];
            op[0] = incx;
            op[1] = incy;
            __threadfence();
            g_status[p] = 2;                       // INCLUSIVE available
        }
        cb.x = __shfl_sync(0xffffffffu, cb.x, 0);
        cb.y = __shfl_sync(0xffffffffu, cb.y, 0);
        // per-warp entering carry values
        float4 ex = shfl_down4(sw, 1);
        if (lane >= NWARPS - 1) ex = ident4();
        float2 wc;
        wc.x = ex.y + ex.x * cb.x;
        wc.y = ex.w + ex.z * cb.y;
        if (lane < NWARPS) WC[lane] = wc;
    }
    __syncthreads();

    float2 wcar = WC[w];
    float4 X = shfl_down4(sfx, 1);
    if (lane == 31) X = ident4();
    float cvt = X.y + X.x * wcar.x;
    float ca  = X.w + X.z * wcar.y;

    float sA = 0.f, sQ = 0.f;
#pragma unroll
    for (int i = ITEMS - 1; i >= 0; i--) {
        if (i < td.nvalid) {
            float a1 = td.a1[i];
            float vt = td.rr[i] + a1 * cvt;
            float A  = td.dd[i] + a1 * TAUF * ca;
            td.rr[i] = vt;
            td.dd[i] = A;
            cvt = vt; ca = A;
            sA += A; sQ += A * A;
        }
    }
    if (td.nvalid == ITEMS) {
#pragma unroll
        for (int j2 = 0; j2 < ITEMS / 4; j2++) {
            *reinterpret_cast<float4*>(outA + s + 4 * j2) =
                make_float4(td.dd[4*j2+0], td.dd[4*j2+1], td.dd[4*j2+2], td.dd[4*j2+3]);
            *reinterpret_cast<float4*>(outVT + s + 4 * j2) =
                make_float4(td.rr[4*j2+0], td.rr[4*j2+1], td.rr[4*j2+2], td.rr[4*j2+3]);
        }
    } else {
        for (int i = 0; i < td.nvalid; i++) {
            outA[s + i]  = td.dd[i];
            outVT[s + i] = td.rr[i];
        }
    }
    // per-block stats
#pragma unroll
    for (int d = 16; d > 0; d >>= 1) {
        sA += __shfl_down_sync(0xffffffffu, sA, d);
        sQ += __shfl_down_sync(0xffffffffu, sQ, d);
    }
    if (lane == 0) WSUM[w] = make_float2(sA, sQ);
    __syncthreads();
    if (w == 0) {
        float2 pp = (lane < NWARPS) ? WSUM[lane] : make_float2(0.f, 0.f);
        float a = pp.x, q = pp.y;
#pragma unroll
        for (int d = NWARPS / 2; d > 0; d >>= 1) {
            a += __shfl_down_sync(0xffffffffu, a, d);
            q += __shfl_down_sync(0xffffffffu, q, d);
        }
        if (lane == 0) g_part[p] = make_float2(a, q);
    }
}

// ---------------- stats: per-block partials -> (mean, inv_std) ----------------
__global__ void __launch_bounds__(1024) k_stats(int NB, long B) {
    __shared__ double DS[32], DQ[32];
    int t = threadIdx.x, lane = t & 31, w = t >> 5;
    double s = 0.0, q = 0.0;
    for (int i = t; i < NB; i += 1024) {
        float2 pp = g_part[i];
        s += (double)pp.x; q += (double)pp.y;
    }
#pragma unroll
    for (int d = 16; d > 0; d >>= 1) {
        s += __shfl_down_sync(0xffffffffu, s, d);
        q += __shfl_down_sync(0xffffffffu, q, d);
    }
    if (lane == 0) { DS[w] = s; DQ[w] = q; }
    __syncthreads();
    if (w == 0) {
        s = DS[lane]; q = DQ[lane];
#pragma unroll
        for (int d = 16; d > 0; d >>= 1) {
            s += __shfl_down_sync(0xffffffffu, s, d);
            q += __shfl_down_sync(0xffffffffu, q, d);
        }
        if (lane == 0) {
            double mean = s / (double)B;
            double var  = (q - s * mean) / (double)(B - 1);
            g_normc = make_float2((float)mean, (float)(1.0 / sqrt(var)));
        }
    }
}

// ---------------- normalize A (L2-hot) ----------------
__global__ void __launch_bounds__(THREADS) k_norm(float* __restrict__ A, long B) {
    float2 nc = g_normc;
    float mean = nc.x, istd = nc.y;
    long n4 = B >> 2;
    long i = (long)blockIdx.x * blockDim.x + threadIdx.x;
    long stride = (long)gridDim.x * blockDim.x;
    float4* A4 = reinterpret_cast<float4*>(A);
    for (; i < n4; i += stride) {
        float4 x = A4[i];
        x.x = (x.x - mean) * istd;
        x.y = (x.y - mean) * istd;
        x.z = (x.z - mean) * istd;
        x.w = (x.w - mean) * istd;
        A4[i] = x;
    }
    long tail = n4 << 2;
    long j = tail + (long)blockIdx.x * blockDim.x + threadIdx.x;
    if (j < B) A[j] = (A[j] - mean) * istd;
}

extern "C" void kernel_launch(void* const* d_in, const int* in_sizes, int n_in,
                              void* d_out, int out_size) {
    const float* r = (const float*)d_in[0];
    const float* v = (const float*)d_in[1];
    const int*   m = (const int*)d_in[2];
    long B = (long)in_sizes[0];
    float* outA  = (float*)d_out;
    float* outVT = outA + B;

    int NB = (int)((B + CHUNK - 1) / CHUNK);
    if (NB > NB_MAX) NB = NB_MAX;   // this problem: NB = 2048

    k_init<<<(NB + 255) / 256, 256>>>(NB);
    k_scan<<<NB, THREADS>>>(r, v, m, outA, outVT, B, NB);
    k_stats<<<1, 1024>>>(NB, B);

    long n4 = (B + 3) / 4;
    int nbn = (int)((n4 + THREADS - 1) / THREADS);
    if (nbn > 4096) nbn = 4096;
    k_norm<<<nbn, THREADS>>>(outA, B);
}

// round 8
// speedup vs baseline: 2.1767x; 2.1767x over previous
#include <cuda_runtime.h>
#include <math.h>

#define GAMMA 0.99f
#define TAUF  0.95f

constexpr int THREADS = 256;
constexpr int ITEMS   = 8;
constexpr int CHUNK   = THREADS * ITEMS;   // 2048
constexpr int NWARPS  = THREADS / 32;      // 8
constexpr int NB_MAX  = 65536;

// Decoupled-lookback state (device globals; no allocation allowed)
__device__ volatile int g_status[NB_MAX];   // 0=invalid 1=aggregate 2=inclusive
__device__ float4 g_agg[NB_MAX];            // block affine summary (av,bv,aa,ba)
__device__ float2 g_incl[NB_MAX];           // inclusive carry VALUE after this block
__device__ float2 g_part[NB_MAX];           // per-block (sumA, sumA2)
__device__ float2 g_normc;                  // (mean, inv_std)
__device__ unsigned int g_done = 0;         // finish counter (reset by last block)

__device__ __forceinline__ float4 ident4() { return make_float4(1.f, 0.f, 1.f, 0.f); }

// lo∘hi: hi applied first. result = f_lo(f_hi(c))
__device__ __forceinline__ float4 comp4(float4 lo, float4 hi) {
    float4 o;
    o.x = lo.x * hi.x;
    o.y = lo.y + lo.x * hi.y;
    o.z = lo.z * hi.z;
    o.w = lo.w + lo.z * hi.w;
    return o;
}

__device__ __forceinline__ float4 shfl_down4(float4 v, int d) {
    float4 o;
    o.x = __shfl_down_sync(0xffffffffu, v.x, d);
    o.y = __shfl_down_sync(0xffffffffu, v.y, d);
    o.z = __shfl_down_sync(0xffffffffu, v.z, d);
    o.w = __shfl_down_sync(0xffffffffu, v.w, d);
    return o;
}

// Inclusive SUFFIX scan within a warp: lane i -> g_i ∘ g_{i+1} ∘ ... ∘ g_31.
// ALL 32 lanes must execute.
__device__ __forceinline__ float4 warp_suffix_scan(float4 v, int lane) {
#pragma unroll
    for (int d = 1; d < 32; d <<= 1) {
        float4 o = shfl_down4(v, d);
        if (lane + d < 32) v = comp4(v, o);
    }
    return v;
}

__device__ __forceinline__ float4 crosswarp_suffix_scan(float4 v, int lane, int n) {
#pragma unroll
    for (int d = 1; d < 32; d <<= 1) {
        if (d >= n) break;
        float4 o = shfl_down4(v, d);
        if (lane + d < n) v = comp4(v, o);
    }
    return v;
}

struct Tile {
    float rr[ITEMS];   // r
    float dd[ITEMS];   // delta
    float a1[ITEMS];   // gamma * mask
    int   nvalid;
};

__device__ __forceinline__ void load_tile(const float* __restrict__ r,
                                          const float* __restrict__ v,
                                          const int*   __restrict__ m,
                                          long s, long B, Tile& td) {
    float vv[ITEMS + 1];
    long rem = B - s;
    td.nvalid = (rem >= ITEMS) ? ITEMS : (rem > 0 ? (int)rem : 0);
    if (td.nvalid == ITEMS) {
#pragma unroll
        for (int j = 0; j < ITEMS / 4; j++) {
            float4 x = *reinterpret_cast<const float4*>(r + s + 4 * j);
            float4 y = *reinterpret_cast<const float4*>(v + s + 4 * j);
            int4  mi = *reinterpret_cast<const int4*>(m + s + 4 * j);
            td.rr[4*j+0] = x.x; td.rr[4*j+1] = x.y; td.rr[4*j+2] = x.z; td.rr[4*j+3] = x.w;
            vv[4*j+0] = y.x; vv[4*j+1] = y.y; vv[4*j+2] = y.z; vv[4*j+3] = y.w;
            td.a1[4*j+0] = GAMMA * (float)mi.x; td.a1[4*j+1] = GAMMA * (float)mi.y;
            td.a1[4*j+2] = GAMMA * (float)mi.z; td.a1[4*j+3] = GAMMA * (float)mi.w;
        }
        vv[ITEMS] = (s + ITEMS < B) ? v[s + ITEMS] : 0.f;
    } else {
#pragma unroll
        for (int i = 0; i < ITEMS; i++) {
            if (i < td.nvalid) {
                td.rr[i] = r[s + i];
                vv[i]    = v[s + i];
                td.a1[i] = GAMMA * (float)m[s + i];
            } else { td.rr[i] = 0.f; vv[i] = 0.f; td.a1[i] = 0.f; }
        }
        vv[ITEMS] = 0.f;
    }
#pragma unroll
    for (int i = 0; i < ITEMS; i++)
        td.dd[i] = td.rr[i] + td.a1[i] * vv[i + 1] - vv[i];
}

__device__ __forceinline__ float4 tile_summary(const Tile& td) {
    float av = 1.f, bv = 0.f, aa = 1.f, ba = 0.f;
#pragma unroll
    for (int i = 0; i < ITEMS; i++) {
        if (i < td.nvalid) {
            float a1 = td.a1[i];
            float a2 = a1 * TAUF;
            bv = bv + av * td.rr[i]; av = av * a1;
            ba = ba + aa * td.dd[i]; aa = aa * a2;
        }
    }
    return make_float4(av, bv, aa, ba);
}

// ---------------- single-pass scan, warp-parallel decoupled lookback ----------------
__global__ void __launch_bounds__(THREADS) k_scan(const float* __restrict__ r,
                                                  const float* __restrict__ v,
                                                  const int* __restrict__ m,
                                                  float* __restrict__ outA,
                                                  float* __restrict__ outVT,
                                                  long B, int NB) {
    __shared__ float4 WAGG[NWARPS];
    __shared__ float2 WC[NWARPS];
    __shared__ float2 WSUM[NWARPS];
    __shared__ int LASTF;
    __shared__ double DS[NWARPS], DQ[NWARPS];
    int t = threadIdx.x, lane = t & 31, w = t >> 5;
    int p = blockIdx.x;                 // processing order
    int ti = NB - 1 - p;                // tile index (reverse scan -> from the end)
    long s = (long)ti * CHUNK + (long)t * ITEMS;

    Tile td;
    load_tile(r, v, m, s, B, td);
    float4 f = tile_summary(td);
    float4 sfx = warp_suffix_scan(f, lane);
    if (lane == 0) WAGG[w] = sfx;
    __syncthreads();

    if (w == 0) {
        float4 sw = (lane < NWARPS) ? WAGG[lane] : ident4();
        sw = crosswarp_suffix_scan(sw, lane, NWARPS);
        float4 F;
        F.x = __shfl_sync(0xffffffffu, sw.x, 0);
        F.y = __shfl_sync(0xffffffffu, sw.y, 0);
        F.z = __shfl_sync(0xffffffffu, sw.z, 0);
        F.w = __shfl_sync(0xffffffffu, sw.w, 0);
        float2 cb = make_float2(0.f, 0.f);
        if (p > 0) {
            if (lane == 0) {
                volatile float* ap = (volatile float*)&g_agg[p];
                ap[0] = F.x; ap[1] = F.y; ap[2] = F.z; ap[3] = F.w;
                __threadfence();
                g_status[p] = 1;                       // AGGREGATE available
            }
            // warp-parallel lookback (32 predecessors per round)
            float4 Hrun = ident4();
            int q = p - 1;
            for (;;) {
                int idx = q - lane;
                int st;
                for (;;) {
                    st = (idx >= 0) ? g_status[idx] : 1;
                    if (!__any_sync(0xffffffffu, st == 0)) break;
                    __nanosleep(20);
                }
                __threadfence();                       // acquire payloads
                bool isinc = (st == 2);
                unsigned ball = __ballot_sync(0xffffffffu, isinc);
                float4 gi;
                if (isinc) {
                    volatile float* ip = (volatile float*)&g_incl[idx];
                    gi = make_float4(0.f, ip[0], 0.f, ip[1]);   // constant map
                } else if (idx >= 0) {
                    volatile float* ap = (volatile float*)&g_agg[idx];
                    gi.x = ap[0]; gi.y = ap[1]; gi.z = ap[2]; gi.w = ap[3];
                } else {
                    gi = ident4();
                }
                if (ball) {
                    int L = __ffs(ball) - 1;           // nearest inclusive
                    if (lane > L) gi = ident4();
                    float4 prod = warp_suffix_scan(gi, lane);  // lane0: window product
                    float4 tot;
                    tot.x = __shfl_sync(0xffffffffu, prod.x, 0);
                    tot.y = __shfl_sync(0xffffffffu, prod.y, 0);
                    tot.z = __shfl_sync(0xffffffffu, prod.z, 0);
                    tot.w = __shfl_sync(0xffffffffu, prod.w, 0);
                    tot = comp4(Hrun, tot);
                    cb = make_float2(tot.y, tot.w);    // constant map -> value
                    break;
                } else {
                    float4 prod = warp_suffix_scan(gi, lane);
                    float4 tot;
                    tot.x = __shfl_sync(0xffffffffu, prod.x, 0);
                    tot.y = __shfl_sync(0xffffffffu, prod.y, 0);
                    tot.z = __shfl_sync(0xffffffffu, prod.z, 0);
                    tot.w = __shfl_sync(0xffffffffu, prod.w, 0);
                    Hrun = comp4(Hrun, tot);
                    q -= 32;
                }
            }
        }
        if (lane == 0) {
            // inclusive value after applying this block
            float incx = F.y + F.x * cb.x;
            float incy = F.w + F.z * cb.y;
            volatile float* op = (volatile float*)&g_incl[p];
            op[0] = incx;
            op[1] = incy;
            __threadfence();
            g_status[p] = 2;                           // INCLUSIVE available
        }
        // per-warp entering carry values
        float4 ex = shfl_down4(sw, 1);
        if (lane >= NWARPS - 1) ex = ident4();
        float2 wc;
        wc.x = ex.y + ex.x * cb.x;
        wc.y = ex.w + ex.z * cb.y;
        if (lane < NWARPS) WC[lane] = wc;
    }
    __syncthreads();

    float2 wcar = WC[w];
    float4 X = shfl_down4(sfx, 1);
    if (lane == 31) X = ident4();
    float cvt = X.y + X.x * wcar.x;
    float ca  = X.w + X.z * wcar.y;

    float sA = 0.f, sQ = 0.f;
#pragma unroll
    for (int i = ITEMS - 1; i >= 0; i--) {
        if (i < td.nvalid) {
            float a1 = td.a1[i];
            float vt = td.rr[i] + a1 * cvt;
            float A  = td.dd[i] + a1 * TAUF * ca;
            td.rr[i] = vt;
            td.dd[i] = A;
            cvt = vt; ca = A;
            sA += A; sQ += A * A;
        }
    }
    if (td.nvalid == ITEMS) {
#pragma unroll
        for (int j2 = 0; j2 < ITEMS / 4; j2++) {
            *reinterpret_cast<float4*>(outA + s + 4 * j2) =
                make_float4(td.dd[4*j2+0], td.dd[4*j2+1], td.dd[4*j2+2], td.dd[4*j2+3]);
            *reinterpret_cast<float4*>(outVT + s + 4 * j2) =
                make_float4(td.rr[4*j2+0], td.rr[4*j2+1], td.rr[4*j2+2], td.rr[4*j2+3]);
        }
    } else {
        for (int i = 0; i < td.nvalid; i++) {
            outA[s + i]  = td.dd[i];
            outVT[s + i] = td.rr[i];
        }
    }
    // per-block stats
#pragma unroll
    for (int d = 16; d > 0; d >>= 1) {
        sA += __shfl_down_sync(0xffffffffu, sA, d);
        sQ += __shfl_down_sync(0xffffffffu, sQ, d);
    }
    if (lane == 0) WSUM[w] = make_float2(sA, sQ);
    __syncthreads();
    if (w == 0) {
        float2 pp = (lane < NWARPS) ? WSUM[lane] : make_float2(0.f, 0.f);
        float a = pp.x, q = pp.y;
#pragma unroll
        for (int d = NWARPS / 2; d > 0; d >>= 1) {
            a += __shfl_down_sync(0xffffffffu, a, d);
            q += __shfl_down_sync(0xffffffffu, q, d);
        }
        if (lane == 0) g_part[p] = make_float2(a, q);
    }
    // last block to finish computes global stats (fused k_stats)
    if (t == 0) {
        __threadfence();
        unsigned int dn = atomicAdd(&g_done, 1);
        LASTF = (dn == (unsigned int)NB - 1) ? 1 : 0;
    }
    __syncthreads();
    if (LASTF) {
        double sd = 0.0, qd = 0.0;
        for (int i = t; i < NB; i += THREADS) {
            float2 pp = g_part[i];
            sd += (double)pp.x; qd += (double)pp.y;
        }
#pragma unroll
        for (int d = 16; d > 0; d >>= 1) {
            sd += __shfl_down_sync(0xffffffffu, sd, d);
            qd += __shfl_down_sync(0xffffffffu, qd, d);
        }
        if (lane == 0) { DS[w] = sd; DQ[w] = qd; }
        __syncthreads();
        if (w == 0) {
            bool ok = lane < NWARPS;
            sd = ok ? DS[lane] : 0.0;
            qd = ok ? DQ[lane] : 0.0;
#pragma unroll
            for (int d = NWARPS / 2; d > 0; d >>= 1) {
                sd += __shfl_down_sync(0xffffffffu, sd, d);
                qd += __shfl_down_sync(0xffffffffu, qd, d);
            }
            if (lane == 0) {
                double mean = sd / (double)B;
                double var  = (qd - sd * mean) / (double)(B - 1);
                g_normc = make_float2((float)mean, (float)(1.0 / sqrt(var)));
                g_done = 0;                        // reset for next replay
            }
        }
    }
}

// ---------------- normalize A (L2-hot) + reset lookback flags for next replay ----------------
__global__ void __launch_bounds__(THREADS) k_norm(float* __restrict__ A, long B, int NB) {
    float2 nc = g_normc;
    float mean = nc.x, istd = nc.y;
    long n4 = B >> 2;
    long gid = (long)blockIdx.x * blockDim.x + threadIdx.x;
    long stride = (long)gridDim.x * blockDim.x;
    float4* A4 = reinterpret_cast<float4*>(A);
    for (long i = gid; i < n4; i += stride) {
        float4 x = A4[i];
        x.x = (x.x - mean) * istd;
        x.y = (x.y - mean) * istd;
        x.z = (x.z - mean) * istd;
        x.w = (x.w - mean) * istd;
        A4[i] = x;
    }
    long tail = n4 << 2;
    long j = tail + gid;
    if (j < B) A[j] = (A[j] - mean) * istd;
    // reset statuses for the next graph replay
    for (long i = gid; i < NB; i += stride) g_status[i] = 0;
}

extern "C" void kernel_launch(void* const* d_in, const int* in_sizes, int n_in,
                              void* d_out, int out_size) {
    const float* r = (const float*)d_in[0];
    const float* v = (const float*)d_in[1];
    const int*   m = (const int*)d_in[2];
    long B = (long)in_sizes[0];
    float* outA  = (float*)d_out;
    float* outVT = outA + B;

    int NB = (int)((B + CHUNK - 1) / CHUNK);
    if (NB > NB_MAX) NB = NB_MAX;   // this problem: NB = 2048

    k_scan<<<NB, THREADS>>>(r, v, m, outA, outVT, B, NB);

    long n4 = (B + 3) / 4;
    int nbn = (int)((n4 + THREADS - 1) / THREADS);
    if (nbn > 4096) nbn = 4096;
    k_norm<<<nbn, THREADS>>>(outA, B, NB);
}